// round 11
// baseline (speedup 1.0000x reference)
#include <cuda_runtime.h>

#define NN 100000
#define NE 640000
#define NF 128
#define NC 16

typedef unsigned long long u64;

// Scratch (allocation-free rule: __device__ globals)
__device__ float g_yl[NN * NC];   // x @ W_l^T
__device__ float g_yr[NN * NC];   // x @ W_r^T
__device__ float g_agg[NN * NC];  // segment-sum of yl over edges
__device__ float g_deg[NN];       // in-degree (float)

__device__ __forceinline__ u64 fma2(u64 a, u64 b, u64 c) {
    u64 d;
    asm("fma.rn.f32x2 %0, %1, %2, %3;" : "=l"(d) : "l"(a), "l"(b), "l"(c));
    return d;
}
__device__ __forceinline__ u64 bcast2(float x) {
    u64 d;
    asm("mov.b64 %0, {%1, %1};" : "=l"(d) : "f"(x));
    return d;
}
__device__ __forceinline__ u64 pack2(float lo, float hi) {
    u64 d;
    asm("mov.b64 %0, {%1, %2};" : "=l"(d) : "f"(lo), "f"(hi));
    return d;
}
__device__ __forceinline__ void unpack2(u64 d, float& lo, float& hi) {
    asm("mov.b64 {%0, %1}, %2;" : "=f"(lo), "=f"(hi) : "l"(d));
}

// ---------------------------------------------------------------------------
// K1: dual projection. Thread = (g = warp-group 0..3, s = lane 0..31).
// Handles 4 nodes (nb + 4s .. +3) x 4 channel-pairs (4g .. 4g+3).
// Per k-pair: 4 broadcast LDS.128 -> 32 fma2  (ratio 8 fma2/LDS; R8 was 4,
// R9's regression was 2 -> L1TEX 84.9%). Whole warp shares g, so every
// weight load is a single-address broadcast. 16 u64 accs -> ~80 regs,
// block 128 -> ~5 CTA/SM. Also zero-inits g_agg/g_deg (replaces k_zero).
// sW2[p][k]: pair p = (W[2p][k], W[2p+1][k]); p<8 -> W_l, p>=8 -> W_r.
// ---------------------------------------------------------------------------
__global__ __launch_bounds__(128, 5) void k_proj(const float* __restrict__ x,
                                                 const float* __restrict__ Wl,
                                                 const float* __restrict__ Wr) {
    __shared__ __align__(16) u64 sW2[16 * NF];  // 16 KB, [p][k]
    int tid = threadIdx.x;
    for (int j = tid; j < 16 * NF; j += 128) {
        int p = j >> 7;
        int k = j & 127;
        const float* r0;
        const float* r1;
        if (p < 8) {
            r0 = Wl + (2 * p) * NF;
            r1 = Wl + (2 * p + 1) * NF;
        } else {
            r0 = Wr + (2 * (p - 8)) * NF;
            r1 = Wr + (2 * (p - 8) + 1) * NF;
        }
        sW2[j] = pack2(r0[k], r1[k]);
    }
    __syncthreads();

    int g = tid >> 5;   // channel-pair quarter (uniform per warp)
    int s = tid & 31;   // node set within block
    int i0 = blockIdx.x * 128 + s * 4;  // this thread's nodes: i0 .. i0+3

    bool v[4];
#pragma unroll
    for (int j = 0; j < 4; j++) v[j] = (i0 + j) < NN;
    if (!v[0]) return;

    // zero-init agg + deg for our nodes (g covers agg cols 4g..4g+3)
#pragma unroll
    for (int j = 0; j < 4; j++) {
        if (v[j]) {
            reinterpret_cast<float4*>(g_agg + (size_t)(i0 + j) * NC)[g] =
                make_float4(0.f, 0.f, 0.f, 0.f);
            if (g == 0) g_deg[i0 + j] = 0.f;
        }
    }

    u64 acc[16];  // [node j][pair pp]
#pragma unroll
    for (int a = 0; a < 16; a++) acc[a] = 0ull;

    const float4* xr[4];
#pragma unroll
    for (int j = 0; j < 4; j++) {
        int idx = v[j] ? (i0 + j) : i0;
        xr[j] = reinterpret_cast<const float4*>(x + (size_t)idx * NF);
    }

    const u64* wb0 = sW2 + (4 * g + 0) * NF;
    const u64* wb1 = sW2 + (4 * g + 1) * NF;
    const u64* wb2 = sW2 + (4 * g + 2) * NF;
    const u64* wb3 = sW2 + (4 * g + 3) * NF;

#pragma unroll 4
    for (int k4 = 0; k4 < 32; k4++) {
        float4 xv0 = xr[0][k4];
        float4 xv1 = xr[1][k4];
        float4 xv2 = xr[2][k4];
        float4 xv3 = xr[3][k4];
#pragma unroll
        for (int h = 0; h < 2; h++) {
            int k = k4 * 4 + h * 2;
            ulonglong2 w0 = *reinterpret_cast<const ulonglong2*>(wb0 + k);
            ulonglong2 w1 = *reinterpret_cast<const ulonglong2*>(wb1 + k);
            ulonglong2 w2 = *reinterpret_cast<const ulonglong2*>(wb2 + k);
            ulonglong2 w3 = *reinterpret_cast<const ulonglong2*>(wb3 + k);
            u64 xa0 = bcast2(h == 0 ? xv0.x : xv0.z);
            u64 xb0 = bcast2(h == 0 ? xv0.y : xv0.w);
            u64 xa1 = bcast2(h == 0 ? xv1.x : xv1.z);
            u64 xb1 = bcast2(h == 0 ? xv1.y : xv1.w);
            u64 xa2 = bcast2(h == 0 ? xv2.x : xv2.z);
            u64 xb2 = bcast2(h == 0 ? xv2.y : xv2.w);
            u64 xa3 = bcast2(h == 0 ? xv3.x : xv3.z);
            u64 xb3 = bcast2(h == 0 ? xv3.y : xv3.w);

            acc[0]  = fma2(xa0, w0.x, acc[0]);   acc[0]  = fma2(xb0, w0.y, acc[0]);
            acc[1]  = fma2(xa0, w1.x, acc[1]);   acc[1]  = fma2(xb0, w1.y, acc[1]);
            acc[2]  = fma2(xa0, w2.x, acc[2]);   acc[2]  = fma2(xb0, w2.y, acc[2]);
            acc[3]  = fma2(xa0, w3.x, acc[3]);   acc[3]  = fma2(xb0, w3.y, acc[3]);
            acc[4]  = fma2(xa1, w0.x, acc[4]);   acc[4]  = fma2(xb1, w0.y, acc[4]);
            acc[5]  = fma2(xa1, w1.x, acc[5]);   acc[5]  = fma2(xb1, w1.y, acc[5]);
            acc[6]  = fma2(xa1, w2.x, acc[6]);   acc[6]  = fma2(xb1, w2.y, acc[6]);
            acc[7]  = fma2(xa1, w3.x, acc[7]);   acc[7]  = fma2(xb1, w3.y, acc[7]);
            acc[8]  = fma2(xa2, w0.x, acc[8]);   acc[8]  = fma2(xb2, w0.y, acc[8]);
            acc[9]  = fma2(xa2, w1.x, acc[9]);   acc[9]  = fma2(xb2, w1.y, acc[9]);
            acc[10] = fma2(xa2, w2.x, acc[10]);  acc[10] = fma2(xb2, w2.y, acc[10]);
            acc[11] = fma2(xa2, w3.x, acc[11]);  acc[11] = fma2(xb2, w3.y, acc[11]);
            acc[12] = fma2(xa3, w0.x, acc[12]);  acc[12] = fma2(xb3, w0.y, acc[12]);
            acc[13] = fma2(xa3, w1.x, acc[13]);  acc[13] = fma2(xb3, w1.y, acc[13]);
            acc[14] = fma2(xa3, w2.x, acc[14]);  acc[14] = fma2(xb3, w2.y, acc[14]);
            acc[15] = fma2(xa3, w3.x, acc[15]);  acc[15] = fma2(xb3, w3.y, acc[15]);
        }
    }

    // Channels 8g..8g+7 of each node: g<2 -> yl (offset 8g), g>=2 -> yr (offset 8g-16)
    float* ybase = (g < 2) ? g_yl : g_yr;
    int coff = (g & 1) * 8;
#pragma unroll
    for (int j = 0; j < 4; j++) {
        if (!v[j]) break;
        float t0, t1, t2, t3, t4, t5, t6, t7;
        unpack2(acc[j * 4 + 0], t0, t1);
        unpack2(acc[j * 4 + 1], t2, t3);
        unpack2(acc[j * 4 + 2], t4, t5);
        unpack2(acc[j * 4 + 3], t6, t7);
        float4* d = reinterpret_cast<float4*>(ybase + (size_t)(i0 + j) * NC + coff);
        d[0] = make_float4(t0, t1, t2, t3);
        d[1] = make_float4(t4, t5, t6, t7);
    }
}

// ---------------------------------------------------------------------------
// K2: edge scatter, 4 threads per edge (thread = edge x quarter-row).
// Each thread: 1 LDG.128 gather + 1 red.global.add.v4.f32; q==0 adds degree.
// ---------------------------------------------------------------------------
__global__ __launch_bounds__(256) void k_scatter(const int* __restrict__ ei) {
    int t = blockIdx.x * blockDim.x + threadIdx.x;
    if (t >= NE * 4) return;
    int e = t >> 2;
    int q = t & 3;
    unsigned src = (unsigned)ei[e];
    unsigned dst = (unsigned)ei[NE + e];
    if (src >= NN || dst >= NN) return;  // never taken with valid input

    float4 v = reinterpret_cast<const float4*>(g_yl)[(size_t)src * 4 + q];
    float* d = g_agg + (size_t)dst * NC + q * 4;
    asm volatile("red.global.add.v4.f32 [%0], {%1, %2, %3, %4};"
                 :: "l"(d), "f"(v.x), "f"(v.y), "f"(v.z), "f"(v.w)
                 : "memory");
    if (q == 0) atomicAdd(&g_deg[dst], 1.0f);
}

// ---------------------------------------------------------------------------
// K3: epilogue, 4 threads per node: out = relu(agg/max(deg,1) + b + yr)
// ---------------------------------------------------------------------------
__global__ __launch_bounds__(256) void k_finish(const float* __restrict__ b,
                                                float* __restrict__ out) {
    int t = blockIdx.x * blockDim.x + threadIdx.x;
    if (t >= NN * 4) return;
    int i = t >> 2;
    int q = t & 3;
    float inv = 1.0f / fmaxf(g_deg[i], 1.0f);

    float4 a = reinterpret_cast<const float4*>(g_agg)[(size_t)i * 4 + q];
    float4 y = reinterpret_cast<const float4*>(g_yr)[(size_t)i * 4 + q];
    float4 bb = reinterpret_cast<const float4*>(b)[q];
    float4 o;
    o.x = fmaxf(fmaf(a.x, inv, bb.x + y.x), 0.f);
    o.y = fmaxf(fmaf(a.y, inv, bb.y + y.y), 0.f);
    o.z = fmaxf(fmaf(a.z, inv, bb.z + y.z), 0.f);
    o.w = fmaxf(fmaf(a.w, inv, bb.w + y.w), 0.f);
    reinterpret_cast<float4*>(out)[(size_t)i * 4 + q] = o;
}

// ---------------------------------------------------------------------------
// Inputs (metadata order): x [N*F] f32, edge_index [2*E] i32,
//                          W_l [C*F] f32, b_l [C] f32, W_r [C*F] f32
// Output: [N*C] f32
// ---------------------------------------------------------------------------
extern "C" void kernel_launch(void* const* d_in, const int* in_sizes, int n_in,
                              void* d_out, int out_size) {
    const float* x = (const float*)d_in[0];
    const int* ei = (const int*)d_in[1];
    const float* Wl = (const float*)d_in[2];
    const float* bl = (const float*)d_in[3];
    const float* Wr = (const float*)d_in[4];
    float* out = (float*)d_out;

    k_proj<<<(NN + 127) / 128, 128>>>(x, Wl, Wr);
    k_scatter<<<(NE * 4 + 255) / 256, 256>>>(ei);
    k_finish<<<(NN * 4 + 255) / 256, 256>>>(bl, out);
}

// round 12
// speedup vs baseline: 1.7407x; 1.7407x over previous
#include <cuda_runtime.h>

#define NN 100000
#define NE 640000
#define NF 128
#define NC 16
#define TILE 256

typedef unsigned long long u64;

// Scratch (allocation-free rule: __device__ globals)
__device__ float g_yl[NN * NC];   // x @ W_l^T
__device__ float g_yr[NN * NC];   // x @ W_r^T
__device__ float g_agg[NN * NC];  // segment-sum of yl over edges
__device__ float g_deg[NN];       // in-degree (float)

__device__ __forceinline__ u64 fma2(u64 a, u64 b, u64 c) {
    u64 d;
    asm("fma.rn.f32x2 %0, %1, %2, %3;" : "=l"(d) : "l"(a), "l"(b), "l"(c));
    return d;
}
__device__ __forceinline__ u64 bcast2(float x) {
    u64 d;
    asm("mov.b64 %0, {%1, %1};" : "=l"(d) : "f"(x));
    return d;
}
__device__ __forceinline__ u64 pack2(float lo, float hi) {
    u64 d;
    asm("mov.b64 %0, {%1, %2};" : "=l"(d) : "f"(lo), "f"(hi));
    return d;
}
__device__ __forceinline__ void unpack2(u64 d, float& lo, float& hi) {
    asm("mov.b64 {%0, %1}, %2;" : "=f"(lo), "=f"(hi) : "l"(d));
}

// ---------------------------------------------------------------------------
// K1: dual projection, 2 nodes/thread (R8 compute shape), x staged via smem.
// The x gather was the L1TEX bottleneck in R8/R9/R10: thread-per-node LDG
// touches 32 lines per warp load. Here a 256-node tile's k-chunk (256x128B)
// is loaded COALESCED into sX (xor-swizzled float4 -> conflict-free LDS in
// the compute phase), 4 chunks of k=32. Weight reads stay single-address
// broadcasts (ratio 4 fma2 per LDS). Also zero-inits g_agg/g_deg.
// sW2[p][k]: pair p = (W[2p][k], W[2p+1][k]); p<8 -> W_l, p>=8 -> W_r.
// ---------------------------------------------------------------------------
__global__ __launch_bounds__(128) void k_proj(const float* __restrict__ x,
                                              const float* __restrict__ Wl,
                                              const float* __restrict__ Wr) {
    __shared__ __align__(16) u64 sW2[16 * NF];    // 16 KB, [p][k]
    __shared__ __align__(16) float4 sX[TILE * 8]; // 16 KB, xor-swizzled
    int tid = threadIdx.x;
    for (int j = tid; j < 16 * NF; j += 128) {
        int p = j >> 7;
        int k = j & 127;
        const float* r0;
        const float* r1;
        if (p < 8) {
            r0 = Wl + (2 * p) * NF;
            r1 = Wl + (2 * p + 1) * NF;
        } else {
            r0 = Wr + (2 * (p - 8)) * NF;
            r1 = Wr + (2 * (p - 8) + 1) * NF;
        }
        sW2[j] = pack2(r0[k], r1[k]);
    }

    int base = blockIdx.x * TILE;
    int i0 = base + tid;
    int i1 = i0 + 128;
    bool v0 = i0 < NN;
    bool v1 = i1 < NN;
    // NOTE: no early return — __syncthreads below needs all threads.

    const float4 z4 = make_float4(0.f, 0.f, 0.f, 0.f);
    if (v0) {
        float4* a = reinterpret_cast<float4*>(g_agg + (size_t)i0 * NC);
        a[0] = z4; a[1] = z4; a[2] = z4; a[3] = z4;
        g_deg[i0] = 0.f;
    }
    if (v1) {
        float4* a = reinterpret_cast<float4*>(g_agg + (size_t)i1 * NC);
        a[0] = z4; a[1] = z4; a[2] = z4; a[3] = z4;
        g_deg[i1] = 0.f;
    }

    u64 acc0[16], acc1[16];
#pragma unroll
    for (int p = 0; p < 16; p++) { acc0[p] = 0ull; acc1[p] = 0ull; }

    const float4* xg = reinterpret_cast<const float4*>(x);  // row stride 32 float4
    int r0 = tid, r1 = tid + 128;

    for (int c = 0; c < 4; c++) {  // k chunks of 32
        __syncthreads();  // previous chunk's sX reads done
        // stage chunk: 256 rows x 8 float4, coalesced LDG
#pragma unroll
        for (int t = tid; t < TILE * 8; t += 128) {
            int row = t >> 3;
            int w = t & 7;
            int gr = base + row;
            float4 val = (gr < NN) ? xg[(size_t)gr * 32 + c * 8 + w] : z4;
            sX[row * 8 + (w ^ (row & 7))] = val;
        }
        __syncthreads();

#pragma unroll
        for (int w = 0; w < 8; w++) {
            float4 xv0 = sX[r0 * 8 + (w ^ (r0 & 7))];
            float4 xv1 = sX[r1 * 8 + (w ^ (r1 & 7))];
#pragma unroll
            for (int h = 0; h < 2; h++) {
                int k = c * 32 + w * 4 + h * 2;
                u64 xa0 = bcast2(h == 0 ? xv0.x : xv0.z);
                u64 xb0 = bcast2(h == 0 ? xv0.y : xv0.w);
                u64 xa1 = bcast2(h == 0 ? xv1.x : xv1.z);
                u64 xb1 = bcast2(h == 0 ? xv1.y : xv1.w);
#pragma unroll
                for (int p = 0; p < 16; p++) {
                    ulonglong2 wv = *reinterpret_cast<const ulonglong2*>(&sW2[p * NF + k]);
                    acc0[p] = fma2(xa0, wv.x, acc0[p]);
                    acc0[p] = fma2(xb0, wv.y, acc0[p]);
                    acc1[p] = fma2(xa1, wv.x, acc1[p]);
                    acc1[p] = fma2(xb1, wv.y, acc1[p]);
                }
            }
        }
    }

    float va[32];
    if (v0) {
#pragma unroll
        for (int p = 0; p < 16; p++) unpack2(acc0[p], va[2 * p], va[2 * p + 1]);
        float4* yl4 = reinterpret_cast<float4*>(g_yl + (size_t)i0 * NC);
        float4* yr4 = reinterpret_cast<float4*>(g_yr + (size_t)i0 * NC);
#pragma unroll
        for (int q = 0; q < 4; q++) {
            yl4[q] = make_float4(va[q * 4 + 0], va[q * 4 + 1], va[q * 4 + 2], va[q * 4 + 3]);
            yr4[q] = make_float4(va[16 + q * 4 + 0], va[16 + q * 4 + 1],
                                 va[16 + q * 4 + 2], va[16 + q * 4 + 3]);
        }
    }
    if (v1) {
#pragma unroll
        for (int p = 0; p < 16; p++) unpack2(acc1[p], va[2 * p], va[2 * p + 1]);
        float4* yl4 = reinterpret_cast<float4*>(g_yl + (size_t)i1 * NC);
        float4* yr4 = reinterpret_cast<float4*>(g_yr + (size_t)i1 * NC);
#pragma unroll
        for (int q = 0; q < 4; q++) {
            yl4[q] = make_float4(va[q * 4 + 0], va[q * 4 + 1], va[q * 4 + 2], va[q * 4 + 3]);
            yr4[q] = make_float4(va[16 + q * 4 + 0], va[16 + q * 4 + 1],
                                 va[16 + q * 4 + 2], va[16 + q * 4 + 3]);
        }
    }
}

// ---------------------------------------------------------------------------
// K2: edge scatter, 4 threads per edge (thread = edge x quarter-row).
// Each thread: 1 LDG.128 gather + 1 red.global.add.v4.f32; q==0 adds degree.
// ---------------------------------------------------------------------------
__global__ __launch_bounds__(256) void k_scatter(const int* __restrict__ ei) {
    int t = blockIdx.x * blockDim.x + threadIdx.x;
    if (t >= NE * 4) return;
    int e = t >> 2;
    int q = t & 3;
    unsigned src = (unsigned)ei[e];
    unsigned dst = (unsigned)ei[NE + e];
    if (src >= NN || dst >= NN) return;  // never taken with valid input

    float4 v = reinterpret_cast<const float4*>(g_yl)[(size_t)src * 4 + q];
    float* d = g_agg + (size_t)dst * NC + q * 4;
    asm volatile("red.global.add.v4.f32 [%0], {%1, %2, %3, %4};"
                 :: "l"(d), "f"(v.x), "f"(v.y), "f"(v.z), "f"(v.w)
                 : "memory");
    if (q == 0) atomicAdd(&g_deg[dst], 1.0f);
}

// ---------------------------------------------------------------------------
// K3: epilogue, 4 threads per node: out = relu(agg/max(deg,1) + b + yr)
// ---------------------------------------------------------------------------
__global__ __launch_bounds__(256) void k_finish(const float* __restrict__ b,
                                                float* __restrict__ out) {
    int t = blockIdx.x * blockDim.x + threadIdx.x;
    if (t >= NN * 4) return;
    int i = t >> 2;
    int q = t & 3;
    float inv = 1.0f / fmaxf(g_deg[i], 1.0f);

    float4 a = reinterpret_cast<const float4*>(g_agg)[(size_t)i * 4 + q];
    float4 y = reinterpret_cast<const float4*>(g_yr)[(size_t)i * 4 + q];
    float4 bb = reinterpret_cast<const float4*>(b)[q];
    float4 o;
    o.x = fmaxf(fmaf(a.x, inv, bb.x + y.x), 0.f);
    o.y = fmaxf(fmaf(a.y, inv, bb.y + y.y), 0.f);
    o.z = fmaxf(fmaf(a.z, inv, bb.z + y.z), 0.f);
    o.w = fmaxf(fmaf(a.w, inv, bb.w + y.w), 0.f);
    reinterpret_cast<float4*>(out)[(size_t)i * 4 + q] = o;
}

// ---------------------------------------------------------------------------
// Inputs (metadata order): x [N*F] f32, edge_index [2*E] i32,
//                          W_l [C*F] f32, b_l [C] f32, W_r [C*F] f32
// Output: [N*C] f32
// ---------------------------------------------------------------------------
extern "C" void kernel_launch(void* const* d_in, const int* in_sizes, int n_in,
                              void* d_out, int out_size) {
    const float* x = (const float*)d_in[0];
    const int* ei = (const int*)d_in[1];
    const float* Wl = (const float*)d_in[2];
    const float* bl = (const float*)d_in[3];
    const float* Wr = (const float*)d_in[4];
    float* out = (float*)d_out;

    k_proj<<<(NN + TILE - 1) / TILE, 128>>>(x, Wl, Wr);
    k_scatter<<<(NE * 4 + 255) / 256, 256>>>(ei);
    k_finish<<<(NN * 4 + 255) / 256, 256>>>(bl, out);
}

// round 13
// speedup vs baseline: 1.7417x; 1.0006x over previous
#include <cuda_runtime.h>

#define NN 100000
#define NE 640000
#define NF 128
#define NC 16
#define TILE 256

typedef unsigned long long u64;

// Scratch (allocation-free rule: __device__ globals)
__device__ float g_yl[NN * NC];   // x @ W_l^T
__device__ float g_yr[NN * NC];   // x @ W_r^T
__device__ float g_agg[NN * NC];  // segment-sum of yl over edges
__device__ float g_deg[NN];       // in-degree (float)

__device__ __forceinline__ u64 fma2(u64 a, u64 b, u64 c) {
    u64 d;
    asm("fma.rn.f32x2 %0, %1, %2, %3;" : "=l"(d) : "l"(a), "l"(b), "l"(c));
    return d;
}
__device__ __forceinline__ u64 bcast2(float x) {
    u64 d;
    asm("mov.b64 %0, {%1, %1};" : "=l"(d) : "f"(x));
    return d;
}
__device__ __forceinline__ u64 pack2(float lo, float hi) {
    u64 d;
    asm("mov.b64 %0, {%1, %2};" : "=l"(d) : "f"(lo), "f"(hi));
    return d;
}
__device__ __forceinline__ void unpack2(u64 d, float& lo, float& hi) {
    asm("mov.b64 {%0, %1}, %2;" : "=f"(lo), "=f"(hi) : "l"(d));
}

// ---------------------------------------------------------------------------
// K1: dual projection. 256-thread block over a 256-node tile.
// Warps 0-3 (half=0) compute yl (channels 0..15); warps 4-7 (half=1) compute
// yr. Each thread: 2 nodes (r, r+128) x 8 channel-pairs -> 16 u64 accs
// (R11 had 32 -> 165 regs -> occ 14.8%; this halves acc state, cap 85 regs,
// 3 CTA/SM = 24 warps). Weight LDS are warp-uniform broadcasts; each
// ulonglong2 load feeds 4 fma2 (2 k-steps x 2 nodes). x rows staged in sX
// (coalesced LDG, xor-swizzled conflict-free LDS). Zero-inits g_agg/g_deg.
// sW2[p][k]: pair p = (W[2p][k], W[2p+1][k]); p<8 -> W_l, p>=8 -> W_r.
// ---------------------------------------------------------------------------
__global__ __launch_bounds__(256, 3) void k_proj(const float* __restrict__ x,
                                                 const float* __restrict__ Wl,
                                                 const float* __restrict__ Wr) {
    __shared__ __align__(16) u64 sW2[16 * NF];    // 16 KB, [p][k]
    __shared__ __align__(16) float4 sX[TILE * 8]; // 16 KB, xor-swizzled
    int tid = threadIdx.x;
    for (int j = tid; j < 16 * NF; j += 256) {
        int p = j >> 7;
        int k = j & 127;
        const float* q0;
        const float* q1;
        if (p < 8) {
            q0 = Wl + (2 * p) * NF;
            q1 = Wl + (2 * p + 1) * NF;
        } else {
            q0 = Wr + (2 * (p - 8)) * NF;
            q1 = Wr + (2 * (p - 8) + 1) * NF;
        }
        sW2[j] = pack2(q0[k], q1[k]);
    }

    int base = blockIdx.x * TILE;
    int half = tid >> 7;        // warp-uniform: 0 -> yl, 1 -> yr
    int r0 = tid & 127;
    int r1 = r0 + 128;
    int n0 = base + r0;
    int n1 = base + r1;
    bool v0 = n0 < NN;
    bool v1 = n1 < NN;
    // NOTE: no early return — __syncthreads below needs all threads.

    const float4 z4 = make_float4(0.f, 0.f, 0.f, 0.f);
    // zero-init agg + deg: thread tid covers tile node base+tid
    {
        int nz = base + tid;
        if (nz < NN) {
            float4* a = reinterpret_cast<float4*>(g_agg + (size_t)nz * NC);
            a[0] = z4; a[1] = z4; a[2] = z4; a[3] = z4;
            g_deg[nz] = 0.f;
        }
    }

    u64 acc[16];  // [node 0/1][pair 0..7]
#pragma unroll
    for (int p = 0; p < 16; p++) acc[p] = 0ull;

    const float4* xg = reinterpret_cast<const float4*>(x);  // row stride 32 float4
    const u64* wb = sW2 + (size_t)half * 8 * NF;

    for (int c = 0; c < 4; c++) {  // k chunks of 32
        __syncthreads();  // previous chunk's sX reads done
#pragma unroll
        for (int t = tid; t < TILE * 8; t += 256) {
            int row = t >> 3;
            int w = t & 7;
            int gr = base + row;
            float4 val = (gr < NN) ? xg[(size_t)gr * 32 + c * 8 + w] : z4;
            sX[row * 8 + (w ^ (row & 7))] = val;
        }
        __syncthreads();

#pragma unroll
        for (int w = 0; w < 8; w++) {
            float4 xv0 = sX[r0 * 8 + (w ^ (r0 & 7))];
            float4 xv1 = sX[r1 * 8 + (w ^ (r1 & 7))];
#pragma unroll
            for (int h = 0; h < 2; h++) {
                int k = c * 32 + w * 4 + h * 2;
                u64 xa0 = bcast2(h == 0 ? xv0.x : xv0.z);
                u64 xb0 = bcast2(h == 0 ? xv0.y : xv0.w);
                u64 xa1 = bcast2(h == 0 ? xv1.x : xv1.z);
                u64 xb1 = bcast2(h == 0 ? xv1.y : xv1.w);
                // two groups of 4 pairs to bound live weight registers
#pragma unroll
                for (int gp = 0; gp < 2; gp++) {
                    ulonglong2 w0 = *reinterpret_cast<const ulonglong2*>(wb + (gp * 4 + 0) * NF + k);
                    ulonglong2 w1 = *reinterpret_cast<const ulonglong2*>(wb + (gp * 4 + 1) * NF + k);
                    ulonglong2 w2 = *reinterpret_cast<const ulonglong2*>(wb + (gp * 4 + 2) * NF + k);
                    ulonglong2 w3 = *reinterpret_cast<const ulonglong2*>(wb + (gp * 4 + 3) * NF + k);
                    int o = gp * 4;
                    acc[o + 0] = fma2(xa0, w0.x, acc[o + 0]);
                    acc[o + 0] = fma2(xb0, w0.y, acc[o + 0]);
                    acc[o + 1] = fma2(xa0, w1.x, acc[o + 1]);
                    acc[o + 1] = fma2(xb0, w1.y, acc[o + 1]);
                    acc[o + 2] = fma2(xa0, w2.x, acc[o + 2]);
                    acc[o + 2] = fma2(xb0, w2.y, acc[o + 2]);
                    acc[o + 3] = fma2(xa0, w3.x, acc[o + 3]);
                    acc[o + 3] = fma2(xb0, w3.y, acc[o + 3]);
                    acc[o + 8] = fma2(xa1, w0.x, acc[o + 8]);
                    acc[o + 8] = fma2(xb1, w0.y, acc[o + 8]);
                    acc[o + 9] = fma2(xa1, w1.x, acc[o + 9]);
                    acc[o + 9] = fma2(xb1, w1.y, acc[o + 9]);
                    acc[o + 10] = fma2(xa1, w2.x, acc[o + 10]);
                    acc[o + 10] = fma2(xb1, w2.y, acc[o + 10]);
                    acc[o + 11] = fma2(xa1, w3.x, acc[o + 11]);
                    acc[o + 11] = fma2(xb1, w3.y, acc[o + 11]);
                }
            }
        }
    }

    float* ybase = (half == 0) ? g_yl : g_yr;
    if (v0) {
        float va[16];
#pragma unroll
        for (int p = 0; p < 8; p++) unpack2(acc[p], va[2 * p], va[2 * p + 1]);
        float4* d = reinterpret_cast<float4*>(ybase + (size_t)n0 * NC);
#pragma unroll
        for (int q = 0; q < 4; q++)
            d[q] = make_float4(va[q * 4 + 0], va[q * 4 + 1], va[q * 4 + 2], va[q * 4 + 3]);
    }
    if (v1) {
        float va[16];
#pragma unroll
        for (int p = 0; p < 8; p++) unpack2(acc[8 + p], va[2 * p], va[2 * p + 1]);
        float4* d = reinterpret_cast<float4*>(ybase + (size_t)n1 * NC);
#pragma unroll
        for (int q = 0; q < 4; q++)
            d[q] = make_float4(va[q * 4 + 0], va[q * 4 + 1], va[q * 4 + 2], va[q * 4 + 3]);
    }
}

// ---------------------------------------------------------------------------
// K2: edge scatter, 4 threads per edge (thread = edge x quarter-row).
// Each thread: 1 LDG.128 gather + 1 red.global.add.v4.f32; q==0 adds degree.
// ---------------------------------------------------------------------------
__global__ __launch_bounds__(256) void k_scatter(const int* __restrict__ ei) {
    int t = blockIdx.x * blockDim.x + threadIdx.x;
    if (t >= NE * 4) return;
    int e = t >> 2;
    int q = t & 3;
    unsigned src = (unsigned)ei[e];
    unsigned dst = (unsigned)ei[NE + e];
    if (src >= NN || dst >= NN) return;  // never taken with valid input

    float4 v = reinterpret_cast<const float4*>(g_yl)[(size_t)src * 4 + q];
    float* d = g_agg + (size_t)dst * NC + q * 4;
    asm volatile("red.global.add.v4.f32 [%0], {%1, %2, %3, %4};"
                 :: "l"(d), "f"(v.x), "f"(v.y), "f"(v.z), "f"(v.w)
                 : "memory");
    if (q == 0) atomicAdd(&g_deg[dst], 1.0f);
}

// ---------------------------------------------------------------------------
// K3: epilogue, 4 threads per node: out = relu(agg/max(deg,1) + b + yr)
// ---------------------------------------------------------------------------
__global__ __launch_bounds__(256) void k_finish(const float* __restrict__ b,
                                                float* __restrict__ out) {
    int t = blockIdx.x * blockDim.x + threadIdx.x;
    if (t >= NN * 4) return;
    int i = t >> 2;
    int q = t & 3;
    float inv = 1.0f / fmaxf(g_deg[i], 1.0f);

    float4 a = reinterpret_cast<const float4*>(g_agg)[(size_t)i * 4 + q];
    float4 y = reinterpret_cast<const float4*>(g_yr)[(size_t)i * 4 + q];
    float4 bb = reinterpret_cast<const float4*>(b)[q];
    float4 o;
    o.x = fmaxf(fmaf(a.x, inv, bb.x + y.x), 0.f);
    o.y = fmaxf(fmaf(a.y, inv, bb.y + y.y), 0.f);
    o.z = fmaxf(fmaf(a.z, inv, bb.z + y.z), 0.f);
    o.w = fmaxf(fmaf(a.w, inv, bb.w + y.w), 0.f);
    reinterpret_cast<float4*>(out)[(size_t)i * 4 + q] = o;
}

// ---------------------------------------------------------------------------
// Inputs (metadata order): x [N*F] f32, edge_index [2*E] i32,
//                          W_l [C*F] f32, b_l [C] f32, W_r [C*F] f32
// Output: [N*C] f32
// ---------------------------------------------------------------------------
extern "C" void kernel_launch(void* const* d_in, const int* in_sizes, int n_in,
                              void* d_out, int out_size) {
    const float* x = (const float*)d_in[0];
    const int* ei = (const int*)d_in[1];
    const float* Wl = (const float*)d_in[2];
    const float* bl = (const float*)d_in[3];
    const float* Wr = (const float*)d_in[4];
    float* out = (float*)d_out;

    k_proj<<<(NN + TILE - 1) / TILE, 256>>>(x, Wl, Wr);
    k_scatter<<<(NE * 4 + 255) / 256, 256>>>(ei);
    k_finish<<<(NN * 4 + 255) / 256, 256>>>(bl, out);
}

// round 14
// speedup vs baseline: 1.7809x; 1.0225x over previous
#include <cuda_runtime.h>

#define NN 100000
#define NE 640000
#define NF 128
#define NC 16
#define TILE 256

typedef unsigned long long u64;

// Scratch (allocation-free rule: __device__ globals)
__device__ float g_yl[NN * NC];   // x @ W_l^T
__device__ float g_yr[NN * NC];   // x @ W_r^T
__device__ float g_agg[NN * NC];  // segment-sum of yl over edges
__device__ float g_deg[NN];       // in-degree (float)

__device__ __forceinline__ u64 fma2(u64 a, u64 b, u64 c) {
    u64 d;
    asm("fma.rn.f32x2 %0, %1, %2, %3;" : "=l"(d) : "l"(a), "l"(b), "l"(c));
    return d;
}
__device__ __forceinline__ u64 bcast2(float x) {
    u64 d;
    asm("mov.b64 %0, {%1, %1};" : "=l"(d) : "f"(x));
    return d;
}
__device__ __forceinline__ u64 pack2(float lo, float hi) {
    u64 d;
    asm("mov.b64 %0, {%1, %2};" : "=l"(d) : "f"(lo), "f"(hi));
    return d;
}
__device__ __forceinline__ void unpack2(u64 d, float& lo, float& hi) {
    asm("mov.b64 {%0, %1}, %2;" : "=f"(lo), "=f"(hi) : "l"(d));
}

// ---------------------------------------------------------------------------
// K1: dual projection. 256-thread block, 256-node tile.
// Thread = (q = tid>>6, r = tid&63): 4 nodes {r, r+64, r+128, r+192} x
// 4 channel-pairs {4q..4q+3} -> 16 u64 accs. Weight LDS per thread drops to
// 256 (ratio 8 fma2/LDS; R12 was 512 @ ratio 4) and __launch_bounds__(256,2)
// (<=128 regs) leaves ~30 regs of slack so ptxas can pipeline weight loads
// over the fma2 blocks — R12's 80-reg cap left LDS latency exposed
// (fma pipe 30.6%, issue 33%). q is warp-uniform -> weight loads stay
// single-address broadcasts. x staged in sX (coalesced LDG, xor-swizzled).
// Zero-inits g_agg/g_deg. sW2[p][k] = (W[2p][k], W[2p+1][k]); p<8 -> W_l.
// ---------------------------------------------------------------------------
__global__ __launch_bounds__(256, 2) void k_proj(const float* __restrict__ x,
                                                 const float* __restrict__ Wl,
                                                 const float* __restrict__ Wr) {
    __shared__ __align__(16) u64 sW2[16 * NF];    // 16 KB, [p][k]
    __shared__ __align__(16) float4 sX[TILE * 8]; // 16 KB, xor-swizzled
    int tid = threadIdx.x;
    for (int j = tid; j < 16 * NF; j += 256) {
        int p = j >> 7;
        int k = j & 127;
        const float* q0;
        const float* q1;
        if (p < 8) {
            q0 = Wl + (2 * p) * NF;
            q1 = Wl + (2 * p + 1) * NF;
        } else {
            q0 = Wr + (2 * (p - 8)) * NF;
            q1 = Wr + (2 * (p - 8) + 1) * NF;
        }
        sW2[j] = pack2(q0[k], q1[k]);
    }

    int base = blockIdx.x * TILE;
    int q = tid >> 6;   // warp-uniform channel-pair quarter
    int r = tid & 63;
    int n[4];
    bool v[4];
#pragma unroll
    for (int j = 0; j < 4; j++) {
        n[j] = base + r + 64 * j;
        v[j] = n[j] < NN;
    }
    // NOTE: no early return — __syncthreads below needs all threads.

    const float4 z4 = make_float4(0.f, 0.f, 0.f, 0.f);
    // zero-init agg + deg: thread tid covers tile node base+tid
    {
        int nz = base + tid;
        if (nz < NN) {
            float4* a = reinterpret_cast<float4*>(g_agg + (size_t)nz * NC);
            a[0] = z4; a[1] = z4; a[2] = z4; a[3] = z4;
            g_deg[nz] = 0.f;
        }
    }

    u64 acc[16];  // [node j][pair p]
#pragma unroll
    for (int p = 0; p < 16; p++) acc[p] = 0ull;

    const float4* xg = reinterpret_cast<const float4*>(x);  // row stride 32 float4
    const u64* wb = sW2 + (size_t)(4 * q) * NF;

    for (int c = 0; c < 4; c++) {  // k chunks of 32
        __syncthreads();  // previous chunk's sX reads done
#pragma unroll
        for (int t = tid; t < TILE * 8; t += 256) {
            int row = t >> 3;
            int w = t & 7;
            int gr = base + row;
            float4 val = (gr < NN) ? xg[(size_t)gr * 32 + c * 8 + w] : z4;
            sX[row * 8 + (w ^ (row & 7))] = val;
        }
        __syncthreads();

#pragma unroll
        for (int w = 0; w < 8; w++) {
            float4 xv[4];
#pragma unroll
            for (int j = 0; j < 4; j++) {
                int row = r + 64 * j;
                xv[j] = sX[row * 8 + (w ^ (row & 7))];
            }
#pragma unroll
            for (int h = 0; h < 2; h++) {
                int k = c * 32 + w * 4 + h * 2;
                ulonglong2 w0 = *reinterpret_cast<const ulonglong2*>(wb + 0 * NF + k);
                ulonglong2 w1 = *reinterpret_cast<const ulonglong2*>(wb + 1 * NF + k);
                ulonglong2 w2 = *reinterpret_cast<const ulonglong2*>(wb + 2 * NF + k);
                ulonglong2 w3 = *reinterpret_cast<const ulonglong2*>(wb + 3 * NF + k);
#pragma unroll
                for (int j = 0; j < 4; j++) {
                    u64 xa = bcast2(h == 0 ? xv[j].x : xv[j].z);
                    u64 xb = bcast2(h == 0 ? xv[j].y : xv[j].w);
                    acc[j * 4 + 0] = fma2(xa, w0.x, acc[j * 4 + 0]);
                    acc[j * 4 + 0] = fma2(xb, w0.y, acc[j * 4 + 0]);
                    acc[j * 4 + 1] = fma2(xa, w1.x, acc[j * 4 + 1]);
                    acc[j * 4 + 1] = fma2(xb, w1.y, acc[j * 4 + 1]);
                    acc[j * 4 + 2] = fma2(xa, w2.x, acc[j * 4 + 2]);
                    acc[j * 4 + 2] = fma2(xb, w2.y, acc[j * 4 + 2]);
                    acc[j * 4 + 3] = fma2(xa, w3.x, acc[j * 4 + 3]);
                    acc[j * 4 + 3] = fma2(xb, w3.y, acc[j * 4 + 3]);
                }
            }
        }
    }

    // Channels 8q..8q+7 of each node: q<2 -> yl (offset 8q), q>=2 -> yr (8q-16)
    float* ybase = (q < 2) ? g_yl : g_yr;
    int coff = (q & 1) * 8;
#pragma unroll
    for (int j = 0; j < 4; j++) {
        if (!v[j]) continue;
        float t0, t1, t2, t3, t4, t5, t6, t7;
        unpack2(acc[j * 4 + 0], t0, t1);
        unpack2(acc[j * 4 + 1], t2, t3);
        unpack2(acc[j * 4 + 2], t4, t5);
        unpack2(acc[j * 4 + 3], t6, t7);
        float4* d = reinterpret_cast<float4*>(ybase + (size_t)n[j] * NC + coff);
        d[0] = make_float4(t0, t1, t2, t3);
        d[1] = make_float4(t4, t5, t6, t7);
    }
}

// ---------------------------------------------------------------------------
// K2: edge scatter, 4 threads per edge (thread = edge x quarter-row).
// Each thread: 1 LDG.128 gather + 1 red.global.add.v4.f32; q==0 adds degree.
// ---------------------------------------------------------------------------
__global__ __launch_bounds__(256) void k_scatter(const int* __restrict__ ei) {
    int t = blockIdx.x * blockDim.x + threadIdx.x;
    if (t >= NE * 4) return;
    int e = t >> 2;
    int q = t & 3;
    unsigned src = (unsigned)ei[e];
    unsigned dst = (unsigned)ei[NE + e];
    if (src >= NN || dst >= NN) return;  // never taken with valid input

    float4 v = reinterpret_cast<const float4*>(g_yl)[(size_t)src * 4 + q];
    float* d = g_agg + (size_t)dst * NC + q * 4;
    asm volatile("red.global.add.v4.f32 [%0], {%1, %2, %3, %4};"
                 :: "l"(d), "f"(v.x), "f"(v.y), "f"(v.z), "f"(v.w)
                 : "memory");
    if (q == 0) atomicAdd(&g_deg[dst], 1.0f);
}

// ---------------------------------------------------------------------------
// K3: epilogue, 4 threads per node: out = relu(agg/max(deg,1) + b + yr)
// ---------------------------------------------------------------------------
__global__ __launch_bounds__(256) void k_finish(const float* __restrict__ b,
                                                float* __restrict__ out) {
    int t = blockIdx.x * blockDim.x + threadIdx.x;
    if (t >= NN * 4) return;
    int i = t >> 2;
    int q = t & 3;
    float inv = 1.0f / fmaxf(g_deg[i], 1.0f);

    float4 a = reinterpret_cast<const float4*>(g_agg)[(size_t)i * 4 + q];
    float4 y = reinterpret_cast<const float4*>(g_yr)[(size_t)i * 4 + q];
    float4 bb = reinterpret_cast<const float4*>(b)[q];
    float4 o;
    o.x = fmaxf(fmaf(a.x, inv, bb.x + y.x), 0.f);
    o.y = fmaxf(fmaf(a.y, inv, bb.y + y.y), 0.f);
    o.z = fmaxf(fmaf(a.z, inv, bb.z + y.z), 0.f);
    o.w = fmaxf(fmaf(a.w, inv, bb.w + y.w), 0.f);
    reinterpret_cast<float4*>(out)[(size_t)i * 4 + q] = o;
}

// ---------------------------------------------------------------------------
// Inputs (metadata order): x [N*F] f32, edge_index [2*E] i32,
//                          W_l [C*F] f32, b_l [C] f32, W_r [C*F] f32
// Output: [N*C] f32
// ---------------------------------------------------------------------------
extern "C" void kernel_launch(void* const* d_in, const int* in_sizes, int n_in,
                              void* d_out, int out_size) {
    const float* x = (const float*)d_in[0];
    const int* ei = (const int*)d_in[1];
    const float* Wl = (const float*)d_in[2];
    const float* bl = (const float*)d_in[3];
    const float* Wr = (const float*)d_in[4];
    float* out = (float*)d_out;

    k_proj<<<(NN + TILE - 1) / TILE, 256>>>(x, Wl, Wr);
    k_scatter<<<(NE * 4 + 255) / 256, 256>>>(ei);
    k_finish<<<(NN * 4 + 255) / 256, 256>>>(bl, out);
}

// round 17
// speedup vs baseline: 1.8077x; 1.0150x over previous
#include <cuda_runtime.h>

#define NN 100000
#define NE 640000
#define NF 128
#define NC 16
#define TILE 256

typedef unsigned long long u64;

// dynamic smem layout: [0,16KB) weights, [16KB,48KB) sX buf0, [48KB,80KB) sX buf1
#define SMEM_W_BYTES (16 * NF * 8)
#define SMEM_X_BYTES (TILE * 8 * 16)
#define SMEM_TOTAL (SMEM_W_BYTES + 2 * SMEM_X_BYTES)

// Scratch (allocation-free rule: __device__ globals)
__device__ float g_yl[NN * NC];   // x @ W_l^T
__device__ float g_yr[NN * NC];   // x @ W_r^T
__device__ float g_agg[NN * NC];  // segment-sum of yl over edges
__device__ float g_deg[NN];       // in-degree (float)

__device__ __forceinline__ u64 fma2(u64 a, u64 b, u64 c) {
    u64 d;
    asm("fma.rn.f32x2 %0, %1, %2, %3;" : "=l"(d) : "l"(a), "l"(b), "l"(c));
    return d;
}
__device__ __forceinline__ u64 bcast2(float x) {
    u64 d;
    asm("mov.b64 %0, {%1, %1};" : "=l"(d) : "f"(x));
    return d;
}
__device__ __forceinline__ u64 pack2(float lo, float hi) {
    u64 d;
    asm("mov.b64 %0, {%1, %2};" : "=l"(d) : "f"(lo), "f"(hi));
    return d;
}
__device__ __forceinline__ void unpack2(u64 d, float& lo, float& hi) {
    asm("mov.b64 {%0, %1}, %2;" : "=f"(lo), "=f"(hi) : "l"(d));
}

// ---------------------------------------------------------------------------
// K1: dual projection, double-buffered cp.async staging (dynamic smem, 80KB —
// static __shared__ capped at 48KB, which broke R14's compile).
// R11-R13 all ran at exactly x-stream rate (51.2MB / 1.35TB/s = 38us): the
// __syncthreads-separated load/compute phases confined DRAM requests to
// short windows. Here chunk c+1 streams via cp.async WHILE chunk c computes
// (wait_group 1 keeps one group in flight), so the DRAM pipe stays busy.
// Compute shape = R13: thread (q=tid>>6, r=tid&63) does 4 nodes x 4
// channel-pairs; weight LDS are warp-uniform broadcasts (ratio 8 fma2/LDS).
// Zero-inits g_agg/g_deg. sW2[p][k] = (W[2p][k], W[2p+1][k]); p<8 -> W_l.
// ---------------------------------------------------------------------------
__global__ __launch_bounds__(256, 2) void k_proj(const float* __restrict__ x,
                                                 const float* __restrict__ Wl,
                                                 const float* __restrict__ Wr) {
    extern __shared__ __align__(16) char smem[];
    u64* sW2 = reinterpret_cast<u64*>(smem);                    // 16 KB, [p][k]
    float4* sXb[2] = {
        reinterpret_cast<float4*>(smem + SMEM_W_BYTES),          // 32 KB
        reinterpret_cast<float4*>(smem + SMEM_W_BYTES + SMEM_X_BYTES)
    };
    int tid = threadIdx.x;
    for (int j = tid; j < 16 * NF; j += 256) {
        int p = j >> 7;
        int k = j & 127;
        const float* q0;
        const float* q1;
        if (p < 8) {
            q0 = Wl + (2 * p) * NF;
            q1 = Wl + (2 * p + 1) * NF;
        } else {
            q0 = Wr + (2 * (p - 8)) * NF;
            q1 = Wr + (2 * (p - 8) + 1) * NF;
        }
        sW2[j] = pack2(q0[k], q1[k]);
    }

    int base = blockIdx.x * TILE;
    int q = tid >> 6;   // warp-uniform channel-pair quarter
    int r = tid & 63;
    int n[4];
    bool v[4];
#pragma unroll
    for (int j = 0; j < 4; j++) {
        n[j] = base + r + 64 * j;
        v[j] = n[j] < NN;
    }
    // NOTE: no early return — __syncthreads below needs all threads.

    const float4 z4 = make_float4(0.f, 0.f, 0.f, 0.f);
    {
        int nz = base + tid;
        if (nz < NN) {
            float4* a = reinterpret_cast<float4*>(g_agg + (size_t)nz * NC);
            a[0] = z4; a[1] = z4; a[2] = z4; a[3] = z4;
            g_deg[nz] = 0.f;
        }
    }

    u64 acc[16];  // [node j][pair p]
#pragma unroll
    for (int p = 0; p < 16; p++) acc[p] = 0ull;

    const float4* xg = reinterpret_cast<const float4*>(x);  // row stride 32 float4
    const u64* wb = sW2 + (size_t)(4 * q) * NF;

    // async stage of chunk c into buffer buf
    auto stage = [&](int c, int buf) {
#pragma unroll
        for (int t = tid; t < TILE * 8; t += 256) {
            int row = t >> 3;
            int w = t & 7;
            int gr = base + row;
            const float4* src = xg + ((size_t)(gr < NN ? gr : 0) * 32 + c * 8 + w);
            unsigned dst = (unsigned)__cvta_generic_to_shared(
                &sXb[buf][row * 8 + (w ^ (row & 7))]);
            int sz = (gr < NN) ? 16 : 0;
            asm volatile("cp.async.ca.shared.global [%0], [%1], 16, %2;"
                         :: "r"(dst), "l"(src), "r"(sz));
        }
        asm volatile("cp.async.commit_group;" ::: "memory");
    };

    stage(0, 0);

    for (int c = 0; c < 4; c++) {
        if (c < 3) {
            stage(c + 1, (c + 1) & 1);
            asm volatile("cp.async.wait_group 1;" ::: "memory");
        } else {
            asm volatile("cp.async.wait_group 0;" ::: "memory");
        }
        __syncthreads();

        const float4* sxb = sXb[c & 1];
#pragma unroll
        for (int w = 0; w < 8; w++) {
            float4 xv[4];
#pragma unroll
            for (int j = 0; j < 4; j++) {
                int row = r + 64 * j;
                xv[j] = sxb[row * 8 + (w ^ (row & 7))];
            }
#pragma unroll
            for (int h = 0; h < 2; h++) {
                int k = c * 32 + w * 4 + h * 2;
                ulonglong2 w0 = *reinterpret_cast<const ulonglong2*>(wb + 0 * NF + k);
                ulonglong2 w1 = *reinterpret_cast<const ulonglong2*>(wb + 1 * NF + k);
                ulonglong2 w2 = *reinterpret_cast<const ulonglong2*>(wb + 2 * NF + k);
                ulonglong2 w3 = *reinterpret_cast<const ulonglong2*>(wb + 3 * NF + k);
#pragma unroll
                for (int j = 0; j < 4; j++) {
                    u64 xa = bcast2(h == 0 ? xv[j].x : xv[j].z);
                    u64 xb = bcast2(h == 0 ? xv[j].y : xv[j].w);
                    acc[j * 4 + 0] = fma2(xa, w0.x, acc[j * 4 + 0]);
                    acc[j * 4 + 0] = fma2(xb, w0.y, acc[j * 4 + 0]);
                    acc[j * 4 + 1] = fma2(xa, w1.x, acc[j * 4 + 1]);
                    acc[j * 4 + 1] = fma2(xb, w1.y, acc[j * 4 + 1]);
                    acc[j * 4 + 2] = fma2(xa, w2.x, acc[j * 4 + 2]);
                    acc[j * 4 + 2] = fma2(xb, w2.y, acc[j * 4 + 2]);
                    acc[j * 4 + 3] = fma2(xa, w3.x, acc[j * 4 + 3]);
                    acc[j * 4 + 3] = fma2(xb, w3.y, acc[j * 4 + 3]);
                }
            }
        }
        __syncthreads();  // compute(c) done before buf[c&1] is overwritten at c+2
    }

    // Channels 8q..8q+7 of each node: q<2 -> yl (offset 8q), q>=2 -> yr (8q-16)
    float* ybase = (q < 2) ? g_yl : g_yr;
    int coff = (q & 1) * 8;
#pragma unroll
    for (int j = 0; j < 4; j++) {
        if (!v[j]) continue;
        float t0, t1, t2, t3, t4, t5, t6, t7;
        unpack2(acc[j * 4 + 0], t0, t1);
        unpack2(acc[j * 4 + 1], t2, t3);
        unpack2(acc[j * 4 + 2], t4, t5);
        unpack2(acc[j * 4 + 3], t6, t7);
        float4* d = reinterpret_cast<float4*>(ybase + (size_t)n[j] * NC + coff);
        d[0] = make_float4(t0, t1, t2, t3);
        d[1] = make_float4(t4, t5, t6, t7);
    }
}

// ---------------------------------------------------------------------------
// K2: edge scatter, 4 threads per edge (thread = edge x quarter-row).
// Each thread: 1 LDG.128 gather + 1 red.global.add.v4.f32; q==0 adds degree.
// ---------------------------------------------------------------------------
__global__ __launch_bounds__(256) void k_scatter(const int* __restrict__ ei) {
    int t = blockIdx.x * blockDim.x + threadIdx.x;
    if (t >= NE * 4) return;
    int e = t >> 2;
    int q = t & 3;
    unsigned src = (unsigned)ei[e];
    unsigned dst = (unsigned)ei[NE + e];
    if (src >= NN || dst >= NN) return;  // never taken with valid input

    float4 v = reinterpret_cast<const float4*>(g_yl)[(size_t)src * 4 + q];
    float* d = g_agg + (size_t)dst * NC + q * 4;
    asm volatile("red.global.add.v4.f32 [%0], {%1, %2, %3, %4};"
                 :: "l"(d), "f"(v.x), "f"(v.y), "f"(v.z), "f"(v.w)
                 : "memory");
    if (q == 0) atomicAdd(&g_deg[dst], 1.0f);
}

// ---------------------------------------------------------------------------
// K3: epilogue, 4 threads per node: out = relu(agg/max(deg,1) + b + yr)
// ---------------------------------------------------------------------------
__global__ __launch_bounds__(256) void k_finish(const float* __restrict__ b,
                                                float* __restrict__ out) {
    int t = blockIdx.x * blockDim.x + threadIdx.x;
    if (t >= NN * 4) return;
    int i = t >> 2;
    int q = t & 3;
    float inv = 1.0f / fmaxf(g_deg[i], 1.0f);

    float4 a = reinterpret_cast<const float4*>(g_agg)[(size_t)i * 4 + q];
    float4 y = reinterpret_cast<const float4*>(g_yr)[(size_t)i * 4 + q];
    float4 bb = reinterpret_cast<const float4*>(b)[q];
    float4 o;
    o.x = fmaxf(fmaf(a.x, inv, bb.x + y.x), 0.f);
    o.y = fmaxf(fmaf(a.y, inv, bb.y + y.y), 0.f);
    o.z = fmaxf(fmaf(a.z, inv, bb.z + y.z), 0.f);
    o.w = fmaxf(fmaf(a.w, inv, bb.w + y.w), 0.f);
    reinterpret_cast<float4*>(out)[(size_t)i * 4 + q] = o;
}

// ---------------------------------------------------------------------------
// Inputs (metadata order): x [N*F] f32, edge_index [2*E] i32,
//                          W_l [C*F] f32, b_l [C] f32, W_r [C*F] f32
// Output: [N*C] f32
// ---------------------------------------------------------------------------
extern "C" void kernel_launch(void* const* d_in, const int* in_sizes, int n_in,
                              void* d_out, int out_size) {
    const float* x = (const float*)d_in[0];
    const int* ei = (const int*)d_in[1];
    const float* Wl = (const float*)d_in[2];
    const float* bl = (const float*)d_in[3];
    const float* Wr = (const float*)d_in[4];
    float* out = (float*)d_out;

    cudaFuncSetAttribute(k_proj, cudaFuncAttributeMaxDynamicSharedMemorySize,
                         SMEM_TOTAL);
    k_proj<<<(NN + TILE - 1) / TILE, 256, SMEM_TOTAL>>>(x, Wl, Wr);
    k_scatter<<<(NE * 4 + 255) / 256, 256>>>(ei);
    k_finish<<<(NN * 4 + 255) / 256, 256>>>(bl, out);
}